// round 15
// baseline (speedup 1.0000x reference)
#include <cuda_runtime.h>

// YOLO loss, sm_103a — round 14: CSPLIT=2 (256 blocks). Per-block fixed costs
// (smem zero, barriers, target scatter, reduce tail) halve again; stream work
// per thread = 40 channels in 4 explicit batches of 10.

#define S_GRID   26
#define NCH      255
#define CELLS    676
#define Q4       169               // CELLS/4
#define BATCH_N  128
#define T_TGT    50
#define L_COORD  5.0f
#define L_NOOBJ  0.5f

#define CSPLIT   2                 // class-channel slices per image (40 ch each)
#define TPB      192
#define NBLOCKS  (BATCH_N * CSPLIT)    // 256

__device__ float    g_acc = 0.0f;      // reset by last block each call
__device__ unsigned g_cnt = 0u;

__global__ __launch_bounds__(TPB)
void yolo_loss_kernel(const float* __restrict__ pred,
                      const float* __restrict__ tgt,
                      float* __restrict__ out)
{
    const int tid = threadIdx.x;
    const int b   = blockIdx.x >> 1;       // image
    const int r   = blockIdx.x & 1;        // slice (0..1)

    __shared__ float s_n[CELLS];
    __shared__ float s_warp[TPB / 32];

    const float* pb  = pred + (size_t)b * NCH * CELLS;
    const float* tgb = tgt  + (size_t)b * T_TGT * 5;

    float sum = 0.0f;
    float4 s = make_float4(0.f, 0.f, 0.f, 0.f);
    float4 cp0 = make_float4(0.f, 0.f, 0.f, 0.f);

    // ===== EARLY ISSUE: stream loads, 4 batches of 10 ======================
    if (tid < Q4) {
        const int j = tid;
        const float4* base = (const float4*)(pb + (size_t)(5 + 40 * r) * CELLS) + j;

        if (r == 0) {
            cp0 = __ldg((const float4*)pb + j);                      // conf0 (masked later)
            const float4 c = __ldg((const float4*)(pb + (size_t)85 * CELLS) + j);
            sum += L_NOOBJ * (c.x*c.x + c.y*c.y + c.z*c.z + c.w*c.w);
        } else {
            const float4 c = __ldg((const float4*)(pb + (size_t)170 * CELLS) + j);
            sum += L_NOOBJ * (c.x*c.x + c.y*c.y + c.z*c.z + c.w*c.w);
        }

        #pragma unroll
        for (int bb = 0; bb < 4; bb++) {
            float4 p[10];
            #pragma unroll
            for (int k = 0; k < 10; k++) p[k] = __ldg(base + (bb * 10 + k) * Q4);
            #pragma unroll
            for (int k = 0; k < 10; k++) {
                s.x = fmaf(p[k].x, p[k].x, s.x);
                s.y = fmaf(p[k].y, p[k].y, s.y);
                s.z = fmaf(p[k].z, p[k].z, s.z);
                s.w = fmaf(p[k].w, p[k].w, s.w);
            }
        }
    }

    // target data (phase-A scatter both slices; gather duty on slice 1)
    float clsf = 0.f, cx = 2.f, cy = 2.f, tw = 0.f, th = 0.f;   // cx=2 -> invalid
    if (tid < T_TGT) {
        clsf = __ldg(tgb + tid * 5 + 0);
        cx   = __ldg(tgb + tid * 5 + 1);
        cy   = __ldg(tgb + tid * 5 + 2);
        tw   = __ldg(tgb + tid * 5 + 3);
        th   = __ldg(tgb + tid * 5 + 4);
    }
    const int gx = (int)(cx * S_GRID);          // trunc == floor (cx >= 0)
    const int gy = (int)(cy * S_GRID);
    const bool tvalid = (tid < T_TGT) && (gx < S_GRID) && (gy < S_GRID);
    const int cell = min(max(gy,0),S_GRID-1) * S_GRID + min(max(gx,0),S_GRID-1);

    if (r == 1 && tvalid) {                     // per-target gather: coord + cls
        const float* cpp = pb + cell;
        const int clsi = (int)clsf;
        const float q1 = __ldg(cpp + (size_t)1 * CELLS);
        const float q2 = __ldg(cpp + (size_t)2 * CELLS);
        const float q3 = __ldg(cpp + (size_t)3 * CELLS);
        const float q4 = __ldg(cpp + (size_t)4 * CELLS);
        const float pg = __ldg(cpp + (size_t)(5 + clsi) * CELLS);
        const float d1 = q1 - cx, d2 = q2 - cy, d3 = q3 - tw, d4 = q4 - th;
        sum += L_COORD * (d1*d1 + d2*d2 + d3*d3 + d4*d4) + 1.0f - 2.0f * pg;
    }

    // ===== PHASE A: per-cell count n (overlapped with in-flight loads) ======
    for (int i = tid; i < CELLS; i += TPB) s_n[i] = 0.0f;
    __syncthreads();
    if (tvalid) atomicAdd(&s_n[cell], 1.0f);
    __syncthreads();

    // ===== COMBINE: apply n to streamed sums ================================
    if (tid < Q4) {
        const float4 nv = *(const float4*)&s_n[4 * tid];
        sum += nv.x * s.x + nv.y * s.y + nv.z * s.z + nv.w * s.w;
        if (r == 0) {
            float t = 0.f;
            t += (nv.x == 0.f) ? cp0.x * cp0.x : 0.f;
            t += (nv.y == 0.f) ? cp0.y * cp0.y : 0.f;
            t += (nv.z == 0.f) ? cp0.z * cp0.z : 0.f;
            t += (nv.w == 0.f) ? cp0.w * cp0.w : 0.f;
            sum += L_NOOBJ * t;
        }
    }

    // ---- block reduce + last-block-done finalization (single launch) ----
    const int lane = tid & 31;
    const int warp = tid >> 5;
    #pragma unroll
    for (int off = 16; off; off >>= 1)
        sum += __shfl_down_sync(0xffffffffu, sum, off);
    if (lane == 0) s_warp[warp] = sum;
    __syncthreads();
    if (tid == 0) {
        float v = s_warp[0];
        #pragma unroll
        for (int w = 1; w < TPB / 32; w++) v += s_warp[w];
        atomicAdd(&g_acc, v);
        __threadfence();
        const unsigned ticket = atomicAdd(&g_cnt, 1u);
        if (ticket == NBLOCKS - 1) {
            const float total = atomicAdd(&g_acc, 0.0f);   // coherent read
            out[0] = total * (1.0f / BATCH_N);
            g_acc = 0.0f;                                  // replay-safe reset
            g_cnt = 0u;
        }
    }
}

extern "C" void kernel_launch(void* const* d_in, const int* in_sizes, int n_in,
                              void* d_out, int out_size)
{
    const float* pred = (const float*)d_in[0];
    const float* tgt  = (const float*)d_in[1];
    float* out = (float*)d_out;

    yolo_loss_kernel<<<NBLOCKS, TPB>>>(pred, tgt, out);
}